// round 5
// baseline (speedup 1.0000x reference)
#include <cuda_runtime.h>

#define N_NODES 100000
#define N_EDGES 1600000
#define HMW 32            // concatenated mu(16) | logstd(16)
#define OUTC 16

// ---------------- scratch (device globals; no allocations allowed) -------------
__device__ float g_deg [N_NODES];          // in-degree count (dst)
__device__ float g_acc0[N_NODES * 2];      // layer-1 aggregation of dis*x
__device__ float g_gvec[N_NODES * HMW];    // g = dis * (h @ [Wmu|Wls])
__device__ float g_acc1[N_NODES * HMW];    // layer-2 aggregation of g[src]
__device__ int   g_is64;                   // edge_index dtype flag

// ---------------- vectorized L2 reductions (sm_90+) -----------------------------
__device__ __forceinline__ void red_add_v4(float* addr, float4 v) {
    asm volatile("red.global.add.v4.f32 [%0], {%1, %2, %3, %4};"
                 :: "l"(addr), "f"(v.x), "f"(v.y), "f"(v.z), "f"(v.w) : "memory");
}
__device__ __forceinline__ void red_add_v2(float* addr, float a, float b) {
    asm volatile("red.global.add.v2.f32 [%0], {%1, %2};"
                 :: "l"(addr), "f"(a), "f"(b) : "memory");
}

__device__ __forceinline__ void load_edge(const void* ei, int e, int& src, int& dst) {
    if (g_is64) {
        const long long* p = (const long long*)ei;
        src = (int)p[e];
        dst = (int)p[N_EDGES + e];
    } else {
        const int* p = (const int*)ei;
        src = p[e];
        dst = p[N_EDGES + e];
    }
}

// ---------------- init: block 0 detects dtype; all blocks zero scratch ----------
// int64 indices < 100000 have all-zero high words -> OR over 4096 words detects.
__global__ void k_init(const unsigned* ei_words) {
    if (blockIdx.x == 0) {
        __shared__ unsigned s_or[256];
        unsigned v = 0;
        for (int i = threadIdx.x; i < 4096; i += 256)
            v |= ei_words[2 * i + 1];
        s_or[threadIdx.x] = v;
        __syncthreads();
        for (int s = 128; s > 0; s >>= 1) {
            if (threadIdx.x < s) s_or[threadIdx.x] |= s_or[threadIdx.x + s];
            __syncthreads();
        }
        if (threadIdx.x == 0) g_is64 = (s_or[0] == 0u) ? 1 : 0;
    }
    const float4 z = make_float4(0.f, 0.f, 0.f, 0.f);
    int i = blockIdx.x * 256 + threadIdx.x;
    if (i < N_NODES * HMW / 4) ((float4*)g_acc1)[i] = z;   // 800000 float4
    if (i < N_NODES * 2 / 4)   ((float4*)g_acc0)[i] = z;   // 50000 float4
    if (i < N_NODES / 4)       ((float4*)g_deg )[i] = z;   // 25000 float4
}

// ---------------- degree (count of dst occurrences) -----------------------------
__global__ void k_deg(const void* ei) {
    int e = blockIdx.x * 256 + threadIdx.x;
    if (e >= N_EDGES) return;
    int dst;
    if (g_is64) dst = (int)((const long long*)ei)[N_EDGES + e];
    else        dst = ((const int*)ei)[N_EDGES + e];
    atomicAdd(&g_deg[dst], 1.0f);
}

// ---------------- layer-1 scatter: acc0[dst] += dis[src] * x[src]  (2 feats) ----
__global__ void k_scatter0(const void* ei, const float* __restrict__ x) {
    int e = blockIdx.x * 256 + threadIdx.x;
    if (e >= N_EDGES) return;
    int src, dst;
    load_edge(ei, e, src, dst);
    float ds = rsqrtf(1.0f + g_deg[src]);
    float2 xv = ((const float2*)x)[src];
    red_add_v2(&g_acc0[2 * dst], ds * xv.x, ds * xv.y);
}

// ---------------- dense: h = relu(aggX @ W1 + b1); g = dis * (h @ [Wmu|Wls]) ----
// TWO THREADS PER NODE (16 outputs each): halves regs and per-thread LDS count,
// doubles warp count -> hides the 29-cyc LDS latency that bound the 1-thr/node
// version at occ=27%. Weights read as broadcast float4 LDS.
__global__ void __launch_bounds__(512) k_hidden(
        const float* __restrict__ x, const float* __restrict__ W1,
        const float* __restrict__ b1,
        const float* __restrict__ Wmu, const float* __restrict__ Wls) {
    __shared__ float4 sW4[64][8];   // [k][j/4] of concatenated [Wmu|Wls], 4KB
    __shared__ float4 sWb[64];      // (W1[0][k], W1[1][k], b1[k], 0)

    int t = threadIdx.x;
    {   // 512 threads load exactly the 512 float4s of [Wmu|Wls]
        int k = t >> 3, q = t & 7;
        sW4[k][q] = (q < 4) ? ((const float4*)Wmu)[k * 4 + q]
                            : ((const float4*)Wls)[k * 4 + (q - 4)];
    }
    if (t < 64) sWb[t] = make_float4(W1[t], W1[64 + t], b1[t], 0.0f);
    __syncthreads();

    int n    = blockIdx.x * 256 + (t >> 1);
    int half = t & 1;                       // 0 -> outputs 0..15, 1 -> 16..31
    if (n >= N_NODES) return;

    float d  = rsqrtf(1.0f + g_deg[n]);
    float d2 = d * d;
    float2 xv = ((const float2*)x)[n];
    float2 av = ((const float2*)g_acc0)[n];
    float a0 = d * av.x + d2 * xv.x;
    float a1 = d * av.y + d2 * xv.y;

    float acc[16];
    #pragma unroll
    for (int j = 0; j < 16; j++) acc[j] = 0.0f;

    int qbase = half * 4;
    #pragma unroll 8
    for (int k = 0; k < 64; k++) {
        float4 wb = sWb[k];
        float hk = fmaxf(0.0f, fmaf(a0, wb.x, fmaf(a1, wb.y, wb.z)));
        #pragma unroll
        for (int qq = 0; qq < 4; qq++) {
            float4 w = sW4[k][qbase + qq];
            acc[qq * 4 + 0] = fmaf(hk, w.x, acc[qq * 4 + 0]);
            acc[qq * 4 + 1] = fmaf(hk, w.y, acc[qq * 4 + 1]);
            acc[qq * 4 + 2] = fmaf(hk, w.z, acc[qq * 4 + 2]);
            acc[qq * 4 + 3] = fmaf(hk, w.w, acc[qq * 4 + 3]);
        }
    }

    float4* gout = (float4*)(g_gvec + n * HMW + half * 16);
    #pragma unroll
    for (int qq = 0; qq < 4; qq++)
        gout[qq] = make_float4(d * acc[qq * 4 + 0], d * acc[qq * 4 + 1],
                               d * acc[qq * 4 + 2], d * acc[qq * 4 + 3]);
}

// ---------------- layer-2 scatter: acc1[dst][:] += g[src][:]  (32 feats) --------
// 8 threads per edge; each does one float4 gather + one independent red.v4
__global__ void k_scatter1(const void* ei) {
    long long tid = (long long)blockIdx.x * 256 + threadIdx.x;
    if (tid >= (long long)N_EDGES * 8) return;
    int e = (int)(tid >> 3), q = (int)(tid & 7);
    int src, dst;
    load_edge(ei, e, src, dst);
    float4 v = ((const float4*)g_gvec)[src * 8 + q];
    red_add_v4(&g_acc1[dst * HMW + q * 4], v);
}

// ---------------- epilogue: out = dis*(acc1 + g) + bias; split mu / logstd ------
__global__ void k_out(const float* __restrict__ bmu, const float* __restrict__ bls,
                      float* __restrict__ out) {
    int tid = blockIdx.x * 256 + threadIdx.x;
    if (tid >= N_NODES * HMW) return;
    int n = tid >> 5, j = tid & 31;
    float v = rsqrtf(1.0f + g_deg[n]) * (g_acc1[tid] + g_gvec[tid]);
    if (j < OUTC) out[n * OUTC + j] = v + bmu[j];
    else          out[N_NODES * OUTC + n * OUTC + (j - OUTC)] = v + bls[j - OUTC];
}

extern "C" void kernel_launch(void* const* d_in, const int* in_sizes, int n_in,
                              void* d_out, int out_size) {
    const float* x    = (const float*)d_in[0];
    const void*  ei   = d_in[1];                 // int32 or int64, detected on device
    const float* W1   = (const float*)d_in[2];
    const float* b1   = (const float*)d_in[3];
    const float* Wmu  = (const float*)d_in[4];
    const float* bmu  = (const float*)d_in[5];
    const float* Wls  = (const float*)d_in[6];
    const float* bls  = (const float*)d_in[7];
    float* out = (float*)d_out;

    const int IB  = (N_NODES * HMW / 4 + 255) / 256;      // 3125 (covers all zeroed ranges)
    const int EB  = (N_EDGES + 255) / 256;                // 6250
    const int HB  = (N_NODES + 255) / 256;                // 391 blocks x 512 thr (2/node)
    const int OB  = (N_NODES * HMW + 255) / 256;          // 12500
    const int S1B = (int)(((long long)N_EDGES * 8 + 255) / 256);  // 50000

    k_init<<<IB, 256>>>((const unsigned*)ei);
    k_deg<<<EB, 256>>>(ei);
    k_scatter0<<<EB, 256>>>(ei, x);
    k_hidden<<<HB, 512>>>(x, W1, b1, Wmu, Wls);
    k_scatter1<<<S1B, 256>>>(ei);
    k_out<<<OB, 256>>>(bmu, bls, out);
}

// round 6
// speedup vs baseline: 1.0859x; 1.0859x over previous
#include <cuda_runtime.h>

#define N_NODES 100000
#define N_EDGES 1600000
#define HMW 32            // concatenated mu(16) | logstd(16)
#define OUTC 16

// ---------------- scratch (device globals; no allocations allowed) -------------
__device__ float g_deg [N_NODES];          // in-degree count (dst)
__device__ float g_acc0[N_NODES * 2];      // layer-1 aggregation of dis*x
__device__ float g_gvec[N_NODES * HMW];    // g = dis * (h @ [Wmu|Wls])
__device__ float g_acc1[N_NODES * HMW];    // layer-2 aggregation of g[src]
__device__ int   g_is64;                   // edge_index dtype flag

// ---------------- vectorized L2 reductions (sm_90+) -----------------------------
__device__ __forceinline__ void red_add_v4(float* addr, float4 v) {
    asm volatile("red.global.add.v4.f32 [%0], {%1, %2, %3, %4};"
                 :: "l"(addr), "f"(v.x), "f"(v.y), "f"(v.z), "f"(v.w) : "memory");
}
__device__ __forceinline__ void red_add_v2(float* addr, float a, float b) {
    asm volatile("red.global.add.v2.f32 [%0], {%1, %2};"
                 :: "l"(addr), "f"(a), "f"(b) : "memory");
}

__device__ __forceinline__ void load_edge(const void* ei, int e, int& src, int& dst) {
    if (g_is64) {
        const long long* p = (const long long*)ei;
        src = (int)p[e];
        dst = (int)p[N_EDGES + e];
    } else {
        const int* p = (const int*)ei;
        src = p[e];
        dst = p[N_EDGES + e];
    }
}

// ---------------- init: block 0 detects dtype; all blocks zero scratch ----------
__global__ void k_init(const unsigned* ei_words) {
    if (blockIdx.x == 0) {
        __shared__ unsigned s_or[256];
        unsigned v = 0;
        for (int i = threadIdx.x; i < 4096; i += 256)
            v |= ei_words[2 * i + 1];
        s_or[threadIdx.x] = v;
        __syncthreads();
        for (int s = 128; s > 0; s >>= 1) {
            if (threadIdx.x < s) s_or[threadIdx.x] |= s_or[threadIdx.x + s];
            __syncthreads();
        }
        if (threadIdx.x == 0) g_is64 = (s_or[0] == 0u) ? 1 : 0;
    }
    const float4 z = make_float4(0.f, 0.f, 0.f, 0.f);
    int i = blockIdx.x * 256 + threadIdx.x;
    if (i < N_NODES * HMW / 4) ((float4*)g_acc1)[i] = z;
    if (i < N_NODES * 2 / 4)   ((float4*)g_acc0)[i] = z;
    if (i < N_NODES / 4)       ((float4*)g_deg )[i] = z;
}

// ---------------- degree (count of dst occurrences) -----------------------------
__global__ void k_deg(const void* ei) {
    int e = blockIdx.x * 256 + threadIdx.x;
    if (e >= N_EDGES) return;
    int dst;
    if (g_is64) dst = (int)((const long long*)ei)[N_EDGES + e];
    else        dst = ((const int*)ei)[N_EDGES + e];
    atomicAdd(&g_deg[dst], 1.0f);
}

// ---------------- layer-1 scatter: acc0[dst] += dis[src] * x[src]  (2 feats) ----
__global__ void k_scatter0(const void* ei, const float* __restrict__ x) {
    int e = blockIdx.x * 256 + threadIdx.x;
    if (e >= N_EDGES) return;
    int src, dst;
    load_edge(ei, e, src, dst);
    float ds = rsqrtf(1.0f + g_deg[src]);
    float2 xv = ((const float2*)x)[src];
    red_add_v2(&g_acc0[2 * dst], ds * xv.x, ds * xv.y);
}

// ---------------- dense: h = relu(aggX @ W1 + b1); g = dis * (h @ [Wmu|Wls]) ----
// 4 threads/node (8 outputs each) x 4 nodes/thread: each loaded weight float4
// feeds 4 nodes -> FMA:LDS ratio 13.3 (was 3.6). 4 independent node chains
// give the ILP to hide LDS latency at the inherent ~5 warps/SMSP.
__global__ void __launch_bounds__(256) k_hidden(
        const float* __restrict__ x, const float* __restrict__ W1,
        const float* __restrict__ b1,
        const float* __restrict__ Wmu, const float* __restrict__ Wls) {
    __shared__ float4 sW4[64][8];   // [k][j/4] of concatenated [Wmu|Wls], 4KB
    __shared__ float4 sWb[64];      // (W1[0][k], W1[1][k], b1[k], 0)

    int t = threadIdx.x;
    for (int i = t; i < 512; i += 256) {
        int k = i >> 3, q = i & 7;
        sW4[k][q] = (q < 4) ? ((const float4*)Wmu)[k * 4 + q]
                            : ((const float4*)Wls)[k * 4 + (q - 4)];
    }
    if (t < 64) sWb[t] = make_float4(W1[t], W1[64 + t], b1[t], 0.0f);
    __syncthreads();

    int part = t & 3;               // which 8 of the 32 outputs
    int u    = t >> 2;              // 0..63
    int base = blockIdx.x * 256;

    float a0[4], a1[4], dd[4];
    #pragma unroll
    for (int i = 0; i < 4; i++) {
        int n = base + u + 64 * i;
        int nc = (n < N_NODES) ? n : 0;
        float d = rsqrtf(1.0f + g_deg[nc]);
        float2 xv = ((const float2*)x)[nc];
        float2 av = ((const float2*)g_acc0)[nc];
        a0[i] = d * av.x + d * d * xv.x;
        a1[i] = d * av.y + d * d * xv.y;
        dd[i] = d;
    }

    float acc[4][8];
    #pragma unroll
    for (int i = 0; i < 4; i++)
        #pragma unroll
        for (int j = 0; j < 8; j++) acc[i][j] = 0.0f;

    int q0 = part * 2;
    #pragma unroll 4
    for (int k = 0; k < 64; k++) {
        float4 wb = sWb[k];
        float4 wA = sW4[k][q0];
        float4 wB = sW4[k][q0 + 1];
        #pragma unroll
        for (int i = 0; i < 4; i++) {
            float hk = fmaxf(0.0f, fmaf(a0[i], wb.x, fmaf(a1[i], wb.y, wb.z)));
            acc[i][0] = fmaf(hk, wA.x, acc[i][0]);
            acc[i][1] = fmaf(hk, wA.y, acc[i][1]);
            acc[i][2] = fmaf(hk, wA.z, acc[i][2]);
            acc[i][3] = fmaf(hk, wA.w, acc[i][3]);
            acc[i][4] = fmaf(hk, wB.x, acc[i][4]);
            acc[i][5] = fmaf(hk, wB.y, acc[i][5]);
            acc[i][6] = fmaf(hk, wB.z, acc[i][6]);
            acc[i][7] = fmaf(hk, wB.w, acc[i][7]);
        }
    }

    #pragma unroll
    for (int i = 0; i < 4; i++) {
        int n = base + u + 64 * i;
        if (n < N_NODES) {
            float4* gout = (float4*)(g_gvec + n * HMW + part * 8);
            gout[0] = make_float4(dd[i] * acc[i][0], dd[i] * acc[i][1],
                                  dd[i] * acc[i][2], dd[i] * acc[i][3]);
            gout[1] = make_float4(dd[i] * acc[i][4], dd[i] * acc[i][5],
                                  dd[i] * acc[i][6], dd[i] * acc[i][7]);
        }
    }
}

// ---------------- layer-2 scatter: acc1[dst][:] += g[src][:]  (32 feats) --------
// 8 threads per edge; each does one float4 gather + one independent red.v4
__global__ void k_scatter1(const void* ei) {
    long long tid = (long long)blockIdx.x * 256 + threadIdx.x;
    if (tid >= (long long)N_EDGES * 8) return;
    int e = (int)(tid >> 3), q = (int)(tid & 7);
    int src, dst;
    load_edge(ei, e, src, dst);
    float4 v = ((const float4*)g_gvec)[src * 8 + q];
    red_add_v4(&g_acc1[dst * HMW + q * 4], v);
}

// ---------------- epilogue: out = dis*(acc1 + g) + bias (float4 throughout) -----
__global__ void k_out(const float* __restrict__ bmu, const float* __restrict__ bls,
                      float* __restrict__ out) {
    int tid = blockIdx.x * 256 + threadIdx.x;       // over N_NODES * 8 float4s
    if (tid >= N_NODES * 8) return;
    int n = tid >> 3, q = tid & 7;
    float d = rsqrtf(1.0f + g_deg[n]);
    float4 a = ((const float4*)g_acc1)[tid];
    float4 g = ((const float4*)g_gvec)[tid];
    float4 b = (q < 4) ? ((const float4*)bmu)[q] : ((const float4*)bls)[q - 4];
    float4 v = make_float4(fmaf(d, a.x + g.x, b.x), fmaf(d, a.y + g.y, b.y),
                           fmaf(d, a.z + g.z, b.z), fmaf(d, a.w + g.w, b.w));
    float* dst = (q < 4) ? out + n * OUTC + q * 4
                         : out + N_NODES * OUTC + n * OUTC + (q - 4) * 4;
    *(float4*)dst = v;
}

extern "C" void kernel_launch(void* const* d_in, const int* in_sizes, int n_in,
                              void* d_out, int out_size) {
    const float* x    = (const float*)d_in[0];
    const void*  ei   = d_in[1];                 // int32 or int64, detected on device
    const float* W1   = (const float*)d_in[2];
    const float* b1   = (const float*)d_in[3];
    const float* Wmu  = (const float*)d_in[4];
    const float* bmu  = (const float*)d_in[5];
    const float* Wls  = (const float*)d_in[6];
    const float* bls  = (const float*)d_in[7];
    float* out = (float*)d_out;

    const int IB  = (N_NODES * HMW / 4 + 255) / 256;      // 3125
    const int EB  = (N_EDGES + 255) / 256;                // 6250
    const int HB  = (N_NODES + 255) / 256;                // 391 blocks x 256 thr
    const int OB  = (N_NODES * 8 + 255) / 256;            // 3125
    const int S1B = (int)(((long long)N_EDGES * 8 + 255) / 256);  // 50000

    k_init<<<IB, 256>>>((const unsigned*)ei);
    k_deg<<<EB, 256>>>(ei);
    k_scatter0<<<EB, 256>>>(ei, x);
    k_hidden<<<HB, 256>>>(x, W1, b1, Wmu, Wls);
    k_scatter1<<<S1B, 256>>>(ei);
    k_out<<<OB, 256>>>(bmu, bls, out);
}